// round 12
// baseline (speedup 1.0000x reference)
#include <cuda_runtime.h>
#include <cuda_fp16.h>
#include <math.h>
#include <stdint.h>

#define N_NODES 100000
#define E_EDGES 1600000
#define NFEAT   512
#define NHID    256
#define NCLASS  40
#define NLAYERS 10
#define ALPHA   0.1f

#define SCAN_BLK 1024
#define NUM_SCAN_BLKS ((N_NODES + SCAN_BLK - 1) / SCAN_BLK)   // 98

// Scratch (static device globals — allocation-free rule)
__device__ __half g_hh[N_NODES * NHID];   // fp16 relu(x@W1+b1)
__device__ float g_h2[N_NODES * NCLASS];  // h@W2+b2  (z_0)
__device__ float g_za[N_NODES * NCLASS];
__device__ float g_zb[N_NODES * NCLASS];

// W1 transposed, fp16: [NHID][NFEAT]
__device__ __half g_w1t[NHID * NFEAT];
// W2 transposed, fp16: [NCLASS][NHID]
__device__ __half g_w2t[NCLASS * NHID];

// CSR build scratch
__device__ int  g_cnt   [N_NODES];
__device__ int  g_offl  [N_NODES];
__device__ int  g_start [N_NODES + 1];
__device__ int  g_cursor[N_NODES];
__device__ int  g_blk   [NUM_SCAN_BLKS];
__device__ int  g_blkoff[NUM_SCAN_BLKS];
__device__ int2 g_edges [E_EDGES];

// ===========================================================================
// helpers (baseline PTX only: ldmatrix / mma.sync / cp.async)
// ===========================================================================
__device__ __forceinline__ uint32_t smem_u32(const void* p) {
    uint32_t a;
    asm("{ .reg .u64 t; cvta.to.shared.u64 t, %1; cvt.u32.u64 %0, t; }"
        : "=r"(a) : "l"(p));
    return a;
}

__device__ __forceinline__ void ldsm4(uint32_t addr, uint32_t* r) {
    asm volatile("ldmatrix.sync.aligned.m8n8.x4.shared.b16 {%0,%1,%2,%3}, [%4];"
        : "=r"(r[0]), "=r"(r[1]), "=r"(r[2]), "=r"(r[3]) : "r"(addr));
}

// fp16 MMA, fp32 accumulate
__device__ __forceinline__ void mma16816(float* c, const uint32_t* a,
                                         uint32_t b0, uint32_t b1) {
    asm volatile(
        "mma.sync.aligned.m16n8k16.row.col.f32.f16.f16.f32 "
        "{%0,%1,%2,%3}, {%4,%5,%6,%7}, {%8,%9}, {%0,%1,%2,%3};"
        : "+f"(c[0]), "+f"(c[1]), "+f"(c[2]), "+f"(c[3])
        : "r"(a[0]), "r"(a[1]), "r"(a[2]), "r"(a[3]), "r"(b0), "r"(b1));
}

__device__ __forceinline__ void cpasync16(uint32_t saddr, const void* gptr) {
    asm volatile("cp.async.cg.shared.global [%0], [%1], 16;"
                 :: "r"(saddr), "l"(gptr) : "memory");
}
#define CP_COMMIT() asm volatile("cp.async.commit_group;" ::: "memory")
#define CP_WAIT0()  asm volatile("cp.async.wait_group 0;" ::: "memory")

__device__ __forceinline__ uint32_t sw128(uint32_t off) {
    return off ^ ((off >> 3) & 0x70);
}

__device__ __forceinline__ uint32_t pack2h(float a, float b) {
    __half2 h = __floats2half2_rn(a, b);
    return *(uint32_t*)&h;
}

// ===========================================================================
// Prep: W1T / W2T fp16
// ===========================================================================
__global__ void prep_w1t_kernel(const float* __restrict__ W1)
{
    int i = blockIdx.x * blockDim.x + threadIdx.x;
    if (i >= NHID * NFEAT) return;
    int n = i / NFEAT, k = i % NFEAT;
    g_w1t[i] = __float2half(W1[(size_t)k * NHID + n]);
}

__global__ void prep_w2t_kernel(const float* __restrict__ W2)
{
    int i = blockIdx.x * blockDim.x + threadIdx.x;
    if (i >= NCLASS * NHID) return;
    int n = i / NHID, k = i % NHID;
    g_w2t[i] = __float2half(W2[(size_t)k * NCLASS + n]);
}

// ===========================================================================
// GEMM1 (mma.sync fp16 x fp16): h = relu(x @ W1 + b1), output fp16
// CTA 64x128, 256 threads / 8 warps (2m x 4n), warp tile 32x32 (acc 32 regs).
// K staged at 64, double buffered, 3 CTAs/SM (smem 48KB/CTA, <=84 regs).
// Two column blocks (blockIdx.y): A read twice (DRAM has headroom).
// ===========================================================================
#define G1_BM 64
#define G1_BN 128
#define G1_BK 64
#define G1_STAGES (NFEAT / G1_BK)      // 8
#define G1_A_OFF 0
#define G1_B_OFF 8192
#define G1_STAGE_BYTES 24576           // 8KB A + 16KB B
#define G1_SMEM (2 * G1_STAGE_BYTES)   // 49152

__global__ void __launch_bounds__(256, 3) gemm1_mma_kernel(
    const float* __restrict__ A,
    const float* __restrict__ bias,
    __half* __restrict__ C)
{
    extern __shared__ char smem[];
    const uint32_t sbase = smem_u32(smem);
    const int tid  = threadIdx.x;
    const int lane = tid & 31;
    const int wid  = tid >> 5;
    const int rowBase = blockIdx.x * G1_BM;
    const int colBase = blockIdx.y * G1_BN;

    const int warp_m = wid & 1;        // 0..1
    const int warp_n = wid >> 1;       // 0..3
    const int m0 = warp_m * 32;
    const int n0 = warp_n * 32;

    float acc[2][4][4];                // mi x (nj*2+hh) x 4
    #pragma unroll
    for (int i = 0; i < 2; i++)
        #pragma unroll
        for (int j = 0; j < 4; j++)
            #pragma unroll
            for (int q = 0; q < 4; q++) acc[i][j][q] = 0.f;

    const int agr = tid >> 2;          // row 0..63
    const int aoq = tid & 3;           // 16-float group within k64

    float a_st[16];

    auto ldgA = [&](int k0) {
        int gr = rowBase + agr;
        if (gr < N_NODES) {
            const float* p = A + (size_t)gr * NFEAT + k0 + aoq * 16;
            #pragma unroll
            for (int v = 0; v < 4; v++) {
                float4 t = *(const float4*)(p + v * 4);
                a_st[v*4+0]=t.x; a_st[v*4+1]=t.y; a_st[v*4+2]=t.z; a_st[v*4+3]=t.w;
            }
        } else {
            #pragma unroll
            for (int q = 0; q < 16; q++) a_st[q] = 0.f;
        }
    };
    auto cpB = [&](int k0, int stage) {
        uint32_t bb = sbase + stage * G1_STAGE_BYTES + G1_B_OFF;
        #pragma unroll
        for (int it = 0; it < 4; it++) {
            int s = tid + it * 256;            // 0..1023
            int n   = s >> 3;                  // 0..127
            int seg = s & 7;
            size_t gi = (size_t)(colBase + n) * NFEAT + k0 + seg * 8;
            uint32_t off = n * 128 + seg * 16;
            cpasync16(bb + sw128(off), g_w1t + gi);
        }
        CP_COMMIT();
    };
    auto stsA = [&](int stage) {
        uint4 q0, q1;
        q0.x = pack2h(a_st[0],  a_st[1]);
        q0.y = pack2h(a_st[2],  a_st[3]);
        q0.z = pack2h(a_st[4],  a_st[5]);
        q0.w = pack2h(a_st[6],  a_st[7]);
        q1.x = pack2h(a_st[8],  a_st[9]);
        q1.y = pack2h(a_st[10], a_st[11]);
        q1.z = pack2h(a_st[12], a_st[13]);
        q1.w = pack2h(a_st[14], a_st[15]);
        uint32_t offh = agr * 128 + aoq * 32;
        char* ab = smem + stage * G1_STAGE_BYTES + G1_A_OFF;
        *(uint4*)(ab + sw128(offh))      = q0;
        *(uint4*)(ab + sw128(offh + 16)) = q1;
    };

    auto compute = [&](int stage) {
        uint32_t ab = sbase + stage * G1_STAGE_BYTES + G1_A_OFF;
        uint32_t bb = sbase + stage * G1_STAGE_BYTES + G1_B_OFF;
        const int q  = lane >> 3;
        const int rr = lane & 7;
        #pragma unroll
        for (int k16 = 0; k16 < 4; k16++) {
            int cb = k16 * 2;
            uint32_t ah[2][4];
            #pragma unroll
            for (int mi = 0; mi < 2; mi++) {
                int row = m0 + mi * 16 + (q & 1) * 8 + rr;
                uint32_t offh = row * 128 + (cb + (q >> 1)) * 16;
                ldsm4(ab + sw128(offh), ah[mi]);
            }
            #pragma unroll
            for (int nj = 0; nj < 2; nj++) {
                uint32_t bh[4];
                int row = n0 + nj * 16 + (q & 1) * 8 + rr;
                uint32_t offh = row * 128 + (cb + (q >> 1)) * 16;
                ldsm4(bb + sw128(offh), bh);
                #pragma unroll
                for (int mi = 0; mi < 2; mi++)
                    #pragma unroll
                    for (int hh = 0; hh < 2; hh++) {
                        float* cc = acc[mi][nj * 2 + hh];
                        mma16816(cc, ah[mi], bh[hh], bh[2 + hh]);
                    }
            }
        }
    };

    ldgA(0); cpB(0, 0); stsA(0);
    CP_WAIT0();
    __syncthreads();

    for (int s = 0; s < G1_STAGES; s++) {
        if (s + 1 < G1_STAGES) {
            ldgA((s + 1) * G1_BK);
            cpB((s + 1) * G1_BK, (s + 1) & 1);
        }
        compute(s & 1);
        if (s + 1 < G1_STAGES) {
            stsA((s + 1) & 1);
            CP_WAIT0();
            __syncthreads();
        }
    }

    const float bval = bias[0];
    const int g  = lane >> 2;
    const int tq = lane & 3;
    #pragma unroll
    for (int mi = 0; mi < 2; mi++)
        #pragma unroll
        for (int nt = 0; nt < 4; nt++) {
            int row = m0 + mi * 16 + g;
            int col = colBase + n0 + nt * 8 + tq * 2;
            int gr0 = rowBase + row;
            int gr1 = gr0 + 8;
            float* cc = acc[mi][nt];
            if (gr0 < N_NODES) {
                uint32_t o = pack2h(fmaxf(cc[0] + bval, 0.f),
                                    fmaxf(cc[1] + bval, 0.f));
                *(uint32_t*)(C + (size_t)gr0 * NHID + col) = o;
            }
            if (gr1 < N_NODES) {
                uint32_t o = pack2h(fmaxf(cc[2] + bval, 0.f),
                                    fmaxf(cc[3] + bval, 0.f));
                *(uint32_t*)(C + (size_t)gr1 * NHID + col) = o;
            }
        }
}

// ===========================================================================
// GEMM2 (mma.sync fp16 x fp16): h2 = h @ W2 + b2
// A (fp16 h) loaded directly via cp.async. CTA 128 rows, 8 warps x 16 rows.
// K = 256 in 4 k64 chunks; W2 chunks smem-resident; A double-buffered.
// ===========================================================================
#define G2_A_ST   16384                 // 128 rows x 128B
#define G2_W2_OFF 32768
#define G2_W2_CH  6144                  // 48 rows x 128B (40 used, pad for ldsm)
#define G2_SMEM   (32768 + 4 * G2_W2_CH)   // 57344

__global__ void __launch_bounds__(256, 1) gemm2_mma_kernel(
    const __half* __restrict__ A,     // g_hh [N, 256]
    const float* __restrict__ bias,
    float* __restrict__ C)            // g_h2 [N, 40]
{
    extern __shared__ char smem[];
    const uint32_t sbase = smem_u32(smem);
    const int tid  = threadIdx.x;
    const int wid  = tid >> 5;
    const int lane = tid & 31;
    const int rowBase = blockIdx.x * 128;
    const int m0 = wid * 16;

    // async-load W2 chunk tiles (4 chunks x 40 rows x 8 segs x 16B)
    for (int idx = tid; idx < 4 * 40 * 8; idx += 256) {
        int ch  = idx / 320;
        int rem = idx - ch * 320;
        int n   = rem >> 3;
        int seg = rem & 7;
        const __half* src = g_w2t + (size_t)n * NHID + ch * 64 + seg * 8;
        uint32_t off = n * 128 + seg * 16;
        cpasync16(sbase + G2_W2_OFF + ch * G2_W2_CH + sw128(off), src);
    }
    CP_COMMIT();

    float acc[5][4];
    #pragma unroll
    for (int j = 0; j < 5; j++)
        #pragma unroll
        for (int q = 0; q < 4; q++) acc[j][q] = 0.f;

    auto cpA = [&](int k0, int stage) {
        uint32_t ab = sbase + stage * G2_A_ST;
        #pragma unroll
        for (int it = 0; it < 4; it++) {
            int s = tid + it * 256;          // 0..1023
            int r   = s >> 3;                // 0..127
            int seg = s & 7;
            int gr = rowBase + r;
            if (gr >= N_NODES) gr = N_NODES - 1;   // clamp (rows unwritten anyway)
            const __half* src = A + (size_t)gr * NHID + k0 + seg * 8;
            uint32_t off = r * 128 + seg * 16;
            cpasync16(ab + sw128(off), src);
        }
        CP_COMMIT();
    };

    auto compute = [&](int stage, int ch) {
        uint32_t ab = sbase + stage * G2_A_ST;
        uint32_t bb = sbase + G2_W2_OFF + ch * G2_W2_CH;
        const int q  = lane >> 3;
        const int rr = lane & 7;
        #pragma unroll
        for (int k16 = 0; k16 < 4; k16++) {
            int cb = k16 * 2;
            uint32_t ah[4];
            {
                int row = m0 + (q & 1) * 8 + rr;
                uint32_t offh = row * 128 + (cb + (q >> 1)) * 16;
                ldsm4(ab + sw128(offh), ah);
            }
            uint32_t bh[3][4];
            #pragma unroll
            for (int nj = 0; nj < 3; nj++) {
                int row = nj * 16 + (q & 1) * 8 + rr;
                uint32_t offh = row * 128 + (cb + (q >> 1)) * 16;
                ldsm4(bb + sw128(offh), bh[nj]);
            }
            #pragma unroll
            for (int nt = 0; nt < 5; nt++) {
                int nj = nt >> 1, hh = nt & 1;
                mma16816(acc[nt], ah, bh[nj][hh], bh[nj][2 + hh]);
            }
        }
    };

    cpA(0, 0);
    CP_WAIT0();        // waits W2 tiles + first A stage
    __syncthreads();

    for (int ch = 0; ch < 4; ch++) {
        if (ch + 1 < 4) cpA((ch + 1) * 64, (ch + 1) & 1);
        compute(ch & 1, ch);
        if (ch + 1 < 4) {
            CP_WAIT0();
            __syncthreads();
        }
    }

    const float bval = bias[0];
    const int g  = lane >> 2;
    const int tq = lane & 3;
    #pragma unroll
    for (int nt = 0; nt < 5; nt++) {
        int col = nt * 8 + tq * 2;
        int gr0 = rowBase + m0 + g;
        int gr1 = gr0 + 8;
        if (gr0 < N_NODES) {
            float2 o; o.x = acc[nt][0] + bval; o.y = acc[nt][1] + bval;
            *(float2*)(C + (size_t)gr0 * NCLASS + col) = o;
        }
        if (gr1 < N_NODES) {
            float2 o; o.x = acc[nt][2] + bval; o.y = acc[nt][3] + bval;
            *(float2*)(C + (size_t)gr1 * NCLASS + col) = o;
        }
    }
}

// ---------------------------------------------------------------------------
// CSR build: histogram -> 2-level exclusive scan -> scatter
// ---------------------------------------------------------------------------
__global__ void zero_counts_kernel()
{
    int i = blockIdx.x * blockDim.x + threadIdx.x;
    if (i < N_NODES) g_cnt[i] = 0;
}

__global__ void histogram_kernel(const int* __restrict__ row)
{
    int e = blockIdx.x * blockDim.x + threadIdx.x;
    if (e < E_EDGES) atomicAdd(&g_cnt[row[e]], 1);
}

__global__ void __launch_bounds__(SCAN_BLK) scan1_kernel()
{
    __shared__ int s[SCAN_BLK];
    int gid = blockIdx.x * SCAN_BLK + threadIdx.x;
    int x = (gid < N_NODES) ? g_cnt[gid] : 0;
    s[threadIdx.x] = x;
    __syncthreads();
    #pragma unroll
    for (int d = 1; d < SCAN_BLK; d <<= 1) {
        int t = (threadIdx.x >= d) ? s[threadIdx.x - d] : 0;
        __syncthreads();
        s[threadIdx.x] += t;
        __syncthreads();
    }
    if (gid < N_NODES) g_offl[gid] = s[threadIdx.x] - x;
    if (threadIdx.x == SCAN_BLK - 1) g_blk[blockIdx.x] = s[SCAN_BLK - 1];
}

__global__ void scan2_kernel()
{
    __shared__ int s[128];
    int tid = threadIdx.x;
    int x = (tid < NUM_SCAN_BLKS) ? g_blk[tid] : 0;
    s[tid] = x;
    __syncthreads();
    #pragma unroll
    for (int d = 1; d < 128; d <<= 1) {
        int t = (tid >= d) ? s[tid - d] : 0;
        __syncthreads();
        s[tid] += t;
        __syncthreads();
    }
    if (tid < NUM_SCAN_BLKS) g_blkoff[tid] = s[tid] - x;
}

__global__ void scan3_kernel()
{
    int i = blockIdx.x * blockDim.x + threadIdx.x;
    if (i < N_NODES) {
        int st = g_offl[i] + g_blkoff[i / SCAN_BLK];
        g_start[i]  = st;
        g_cursor[i] = st;
    }
    if (i == 0) g_start[N_NODES] = E_EDGES;
}

__global__ void scatter_kernel(const int* __restrict__ row,
                               const int* __restrict__ col,
                               const float* __restrict__ vals)
{
    int e = blockIdx.x * blockDim.x + threadIdx.x;
    if (e >= E_EDGES) return;
    int r = row[e];
    int pos = atomicAdd(&g_cursor[r], 1);
    int2 ev;
    ev.x = col[e];
    ev.y = __float_as_int((1.0f - ALPHA) * vals[e]);
    g_edges[pos] = ev;
}

// ---------------------------------------------------------------------------
// Pull-mode SpMM: 10 threads per row, one float4 segment per thread.
// ---------------------------------------------------------------------------
#define SPMM_TPB 320

__global__ void __launch_bounds__(SPMM_TPB) spmm_csr_kernel(
    const float* __restrict__ z,
    const float* __restrict__ h2,
    float* __restrict__ znew)
{
    int t = blockIdx.x * SPMM_TPB + threadIdx.x;
    int r   = t / 10;
    int seg = t - r * 10;
    if (r >= N_NODES) return;

    int e0 = g_start[r];
    int e1 = g_start[r + 1];

    float4 acc = make_float4(0.f, 0.f, 0.f, 0.f);

    int e = e0;
    for (; e + 2 <= e1; e += 2) {
        int2 ev0 = __ldg(&g_edges[e]);
        int2 ev1 = __ldg(&g_edges[e + 1]);
        float v0 = __int_as_float(ev0.y);
        float v1 = __int_as_float(ev1.y);
        float4 a0 = __ldg((const float4*)(z + (size_t)ev0.x * NCLASS) + seg);
        float4 a1 = __ldg((const float4*)(z + (size_t)ev1.x * NCLASS) + seg);
        acc.x += v0 * a0.x + v1 * a1.x;
        acc.y += v0 * a0.y + v1 * a1.y;
        acc.z += v0 * a0.z + v1 * a1.z;
        acc.w += v0 * a0.w + v1 * a1.w;
    }
    if (e < e1) {
        int2 ev = __ldg(&g_edges[e]);
        float v = __int_as_float(ev.y);
        float4 a = __ldg((const float4*)(z + (size_t)ev.x * NCLASS) + seg);
        acc.x += v * a.x;
        acc.y += v * a.y;
        acc.z += v * a.z;
        acc.w += v * a.w;
    }

    float4 hv = __ldg((const float4*)(h2 + (size_t)r * NCLASS) + seg);
    float4 o;
    o.x = acc.x + ALPHA * hv.x;
    o.y = acc.y + ALPHA * hv.y;
    o.z = acc.z + ALPHA * hv.z;
    o.w = acc.w + ALPHA * hv.w;
    ((float4*)(znew + (size_t)r * NCLASS))[seg] = o;
}

// ---------------------------------------------------------------------------
// Row-wise log_softmax over 40 classes: one warp per row
// ---------------------------------------------------------------------------
__global__ void logsoftmax_kernel(const float* __restrict__ z,
                                  float* __restrict__ out)
{
    int gtid = blockIdx.x * blockDim.x + threadIdx.x;
    int warp = gtid / 32;
    int lane = gtid % 32;
    if (warp >= N_NODES) return;

    const float* zr = z + (size_t)warp * NCLASS;
    float v0 = zr[lane];
    float v1 = (lane < NCLASS - 32) ? zr[lane + 32] : -INFINITY;

    float m = fmaxf(v0, v1);
    #pragma unroll
    for (int o = 16; o > 0; o >>= 1)
        m = fmaxf(m, __shfl_xor_sync(0xFFFFFFFFu, m, o));

    float s = expf(v0 - m) + ((lane < NCLASS - 32) ? expf(v1 - m) : 0.f);
    #pragma unroll
    for (int o = 16; o > 0; o >>= 1)
        s += __shfl_xor_sync(0xFFFFFFFFu, s, o);

    float L = m + logf(s);
    out[(size_t)warp * NCLASS + lane] = v0 - L;
    if (lane < NCLASS - 32)
        out[(size_t)warp * NCLASS + lane + 32] = v1 - L;
}

// ---------------------------------------------------------------------------
extern "C" void kernel_launch(void* const* d_in, const int* in_sizes, int n_in,
                              void* d_out, int out_size)
{
    const float* x    = (const float*)d_in[0];
    const int*   row  = (const int*)  d_in[1];
    const int*   col  = (const int*)  d_in[2];
    const float* vals = (const float*)d_in[3];
    const float* W1   = (const float*)d_in[4];
    const float* b1   = (const float*)d_in[5];
    const float* W2   = (const float*)d_in[6];
    const float* b2   = (const float*)d_in[7];
    float* out = (float*)d_out;

    __half* hh;
    float *h2, *za, *zb;
    cudaGetSymbolAddress((void**)&hh, g_hh);
    cudaGetSymbolAddress((void**)&h2, g_h2);
    cudaGetSymbolAddress((void**)&za, g_za);
    cudaGetSymbolAddress((void**)&zb, g_zb);

    cudaFuncSetAttribute(gemm1_mma_kernel,
                         cudaFuncAttributeMaxDynamicSharedMemorySize, G1_SMEM);
    cudaFuncSetAttribute(gemm2_mma_kernel,
                         cudaFuncAttributeMaxDynamicSharedMemorySize, G2_SMEM);

    // Launch order: gemm1 is our 4th launch (ncu profiles our #4).
    prep_w1t_kernel<<<(NHID * NFEAT + 255) / 256, 256>>>(W1);              // 1
    prep_w2t_kernel<<<(NCLASS * NHID + 255) / 256, 256>>>(W2);             // 2
    zero_counts_kernel<<<(N_NODES + 255) / 256, 256>>>();                  // 3
    dim3 g1grid((N_NODES + G1_BM - 1) / G1_BM, NHID / G1_BN);
    gemm1_mma_kernel<<<g1grid, 256, G1_SMEM>>>(x, b1, hh);                 // 4
    histogram_kernel<<<(E_EDGES + 255) / 256, 256>>>(row);                 // 5
    scan1_kernel<<<NUM_SCAN_BLKS, SCAN_BLK>>>();                           // 6
    scan2_kernel<<<1, 128>>>();                                            // 7
    scan3_kernel<<<(N_NODES + 255) / 256, 256>>>();                        // 8
    scatter_kernel<<<(E_EDGES + 255) / 256, 256>>>(row, col, vals);        // 9
    gemm2_mma_kernel<<<(N_NODES + 127) / 128, 256, G2_SMEM>>>(hh, b2, h2); // 10

    // APPNP propagation
    const int spmm_grid = (N_NODES * 10 + SPMM_TPB - 1) / SPMM_TPB;
    const float* zin = h2;
    float* bufs[2] = { za, zb };
    for (int it = 0; it < NLAYERS; it++) {
        float* zout = bufs[it & 1];
        spmm_csr_kernel<<<spmm_grid, SPMM_TPB>>>(zin, h2, zout);
        zin = zout;
    }

    logsoftmax_kernel<<<(N_NODES * 32 + 255) / 256, 256>>>(zin, out);
}

// round 13
// speedup vs baseline: 1.0759x; 1.0759x over previous
#include <cuda_runtime.h>
#include <cuda_fp16.h>
#include <math.h>
#include <stdint.h>

#define N_NODES 100000
#define E_EDGES 1600000
#define NFEAT   512
#define NHID    256
#define NCLASS  40
#define NLAYERS 10
#define ALPHA   0.1f

#define SCAN_BLK 1024
#define NUM_SCAN_BLKS ((N_NODES + SCAN_BLK - 1) / SCAN_BLK)   // 98

// Scratch (static device globals — allocation-free rule)
__device__ __half g_hh[N_NODES * NHID];   // fp16 relu(x@W1+b1)
__device__ float g_h2[N_NODES * NCLASS];  // h@W2+b2  (z_0)
__device__ float g_za[N_NODES * NCLASS];
__device__ float g_zb[N_NODES * NCLASS];

// W1 transposed, fp16: [NHID][NFEAT]
__device__ __half g_w1t[NHID * NFEAT];
// W2 transposed, fp16: [NCLASS][NHID]
__device__ __half g_w2t[NCLASS * NHID];

// CSR build scratch
__device__ int  g_cnt   [N_NODES];
__device__ int  g_offl  [N_NODES];
__device__ int  g_start [N_NODES + 1];
__device__ int  g_cursor[N_NODES];
__device__ int  g_blk   [NUM_SCAN_BLKS];
__device__ int  g_blkoff[NUM_SCAN_BLKS];
__device__ int2 g_edges [E_EDGES];

// ===========================================================================
// helpers (baseline PTX only: ldmatrix / mma.sync / cp.async)
// ===========================================================================
__device__ __forceinline__ uint32_t smem_u32(const void* p) {
    uint32_t a;
    asm("{ .reg .u64 t; cvta.to.shared.u64 t, %1; cvt.u32.u64 %0, t; }"
        : "=r"(a) : "l"(p));
    return a;
}

__device__ __forceinline__ void ldsm4(uint32_t addr, uint32_t* r) {
    asm volatile("ldmatrix.sync.aligned.m8n8.x4.shared.b16 {%0,%1,%2,%3}, [%4];"
        : "=r"(r[0]), "=r"(r[1]), "=r"(r[2]), "=r"(r[3]) : "r"(addr));
}

// fp16 MMA, fp32 accumulate
__device__ __forceinline__ void mma16816(float* c, const uint32_t* a,
                                         uint32_t b0, uint32_t b1) {
    asm volatile(
        "mma.sync.aligned.m16n8k16.row.col.f32.f16.f16.f32 "
        "{%0,%1,%2,%3}, {%4,%5,%6,%7}, {%8,%9}, {%0,%1,%2,%3};"
        : "+f"(c[0]), "+f"(c[1]), "+f"(c[2]), "+f"(c[3])
        : "r"(a[0]), "r"(a[1]), "r"(a[2]), "r"(a[3]), "r"(b0), "r"(b1));
}

__device__ __forceinline__ void cpasync16(uint32_t saddr, const void* gptr) {
    asm volatile("cp.async.cg.shared.global [%0], [%1], 16;"
                 :: "r"(saddr), "l"(gptr) : "memory");
}
#define CP_COMMIT() asm volatile("cp.async.commit_group;" ::: "memory")
#define CP_WAIT0()  asm volatile("cp.async.wait_group 0;" ::: "memory")

__device__ __forceinline__ uint32_t sw128(uint32_t off) {
    return off ^ ((off >> 3) & 0x70);
}

__device__ __forceinline__ uint32_t pack2h(float a, float b) {
    __half2 h = __floats2half2_rn(a, b);
    return *(uint32_t*)&h;
}

// ===========================================================================
// Prep: W1T / W2T fp16
// ===========================================================================
__global__ void prep_w1t_kernel(const float* __restrict__ W1)
{
    int i = blockIdx.x * blockDim.x + threadIdx.x;
    if (i >= NHID * NFEAT) return;
    int n = i / NFEAT, k = i % NFEAT;
    g_w1t[i] = __float2half(W1[(size_t)k * NHID + n]);
}

__global__ void prep_w2t_kernel(const float* __restrict__ W2)
{
    int i = blockIdx.x * blockDim.x + threadIdx.x;
    if (i >= NCLASS * NHID) return;
    int n = i / NHID, k = i % NHID;
    g_w2t[i] = __float2half(W2[(size_t)k * NCLASS + n]);
}

// ===========================================================================
// GEMM1 (mma.sync fp16 x fp16): h = relu(x @ W1 + b1), output fp16
// CTA 64x256, 256 threads / 8 warps (2m x 4n), warp tile 32x64.
// K staged at 64, double buffered smem, 2 CTAs/SM.
// B fragments double-buffered in registers (prefetch next k16 before MMAs).
// ===========================================================================
#define G1_BM 64
#define G1_BN 256
#define G1_BK 64
#define G1_STAGES (NFEAT / G1_BK)      // 8
#define G1_A_OFF 0
#define G1_B_OFF 8192
#define G1_STAGE_BYTES 40960           // 8KB A + 32KB B
#define G1_SMEM (2 * G1_STAGE_BYTES)   // 81920

__global__ void __launch_bounds__(256, 2) gemm1_mma_kernel(
    const float* __restrict__ A,
    const float* __restrict__ bias,
    __half* __restrict__ C)
{
    extern __shared__ char smem[];
    const uint32_t sbase = smem_u32(smem);
    const int tid  = threadIdx.x;
    const int lane = tid & 31;
    const int wid  = tid >> 5;
    const int rowBase = blockIdx.x * G1_BM;

    const int warp_m = wid & 1;        // 0..1
    const int warp_n = wid >> 1;       // 0..3
    const int m0 = warp_m * 32;
    const int n0 = warp_n * 64;

    float acc[2][8][4];
    #pragma unroll
    for (int i = 0; i < 2; i++)
        #pragma unroll
        for (int j = 0; j < 8; j++)
            #pragma unroll
            for (int q = 0; q < 4; q++) acc[i][j][q] = 0.f;

    const int agr = tid >> 2;          // row 0..63
    const int aoq = tid & 3;           // 16-float group within k64

    float a_st[16];

    auto ldgA = [&](int k0) {
        int gr = rowBase + agr;
        if (gr < N_NODES) {
            const float* p = A + (size_t)gr * NFEAT + k0 + aoq * 16;
            #pragma unroll
            for (int v = 0; v < 4; v++) {
                float4 t = *(const float4*)(p + v * 4);
                a_st[v*4+0]=t.x; a_st[v*4+1]=t.y; a_st[v*4+2]=t.z; a_st[v*4+3]=t.w;
            }
        } else {
            #pragma unroll
            for (int q = 0; q < 16; q++) a_st[q] = 0.f;
        }
    };
    auto cpB = [&](int k0, int stage) {
        uint32_t bb = sbase + stage * G1_STAGE_BYTES + G1_B_OFF;
        #pragma unroll
        for (int it = 0; it < 8; it++) {
            int s = tid + it * 256;            // 0..2047
            int n   = s >> 3;                  // 0..255
            int seg = s & 7;
            size_t gi = (size_t)n * NFEAT + k0 + seg * 8;
            uint32_t off = n * 128 + seg * 16;
            cpasync16(bb + sw128(off), g_w1t + gi);
        }
        CP_COMMIT();
    };
    auto stsA = [&](int stage) {
        uint4 q0, q1;
        q0.x = pack2h(a_st[0],  a_st[1]);
        q0.y = pack2h(a_st[2],  a_st[3]);
        q0.z = pack2h(a_st[4],  a_st[5]);
        q0.w = pack2h(a_st[6],  a_st[7]);
        q1.x = pack2h(a_st[8],  a_st[9]);
        q1.y = pack2h(a_st[10], a_st[11]);
        q1.z = pack2h(a_st[12], a_st[13]);
        q1.w = pack2h(a_st[14], a_st[15]);
        uint32_t offh = agr * 128 + aoq * 32;
        char* ab = smem + stage * G1_STAGE_BYTES + G1_A_OFF;
        *(uint4*)(ab + sw128(offh))      = q0;
        *(uint4*)(ab + sw128(offh + 16)) = q1;
    };

    auto compute = [&](int stage) {
        uint32_t ab = sbase + stage * G1_STAGE_BYTES + G1_A_OFF;
        uint32_t bb = sbase + stage * G1_STAGE_BYTES + G1_B_OFF;
        const int q  = lane >> 3;
        const int rr = lane & 7;

        uint32_t bf[2][4][4];   // double-buffered B fragments
        // preload k16=0 B frags
        #pragma unroll
        for (int nj = 0; nj < 4; nj++) {
            int row = n0 + nj * 16 + (q & 1) * 8 + rr;
            uint32_t offh = row * 128 + (q >> 1) * 16;
            ldsm4(bb + sw128(offh), bf[0][nj]);
        }
        #pragma unroll
        for (int k16 = 0; k16 < 4; k16++) {
            int cur = k16 & 1;
            // prefetch next k16's B frags before issuing current MMAs
            if (k16 < 3) {
                int cbn = (k16 + 1) * 2;
                #pragma unroll
                for (int nj = 0; nj < 4; nj++) {
                    int row = n0 + nj * 16 + (q & 1) * 8 + rr;
                    uint32_t offh = row * 128 + (cbn + (q >> 1)) * 16;
                    ldsm4(bb + sw128(offh), bf[cur ^ 1][nj]);
                }
            }
            int cb = k16 * 2;
            uint32_t ah[2][4];
            #pragma unroll
            for (int mi = 0; mi < 2; mi++) {
                int row = m0 + mi * 16 + (q & 1) * 8 + rr;
                uint32_t offh = row * 128 + (cb + (q >> 1)) * 16;
                ldsm4(ab + sw128(offh), ah[mi]);
            }
            #pragma unroll
            for (int nj = 0; nj < 4; nj++)
                #pragma unroll
                for (int mi = 0; mi < 2; mi++)
                    #pragma unroll
                    for (int hh = 0; hh < 2; hh++) {
                        float* cc = acc[mi][nj * 2 + hh];
                        mma16816(cc, ah[mi], bf[cur][nj][hh], bf[cur][nj][2 + hh]);
                    }
        }
    };

    ldgA(0); cpB(0, 0); stsA(0);
    CP_WAIT0();
    __syncthreads();

    for (int s = 0; s < G1_STAGES; s++) {
        if (s + 1 < G1_STAGES) {
            ldgA((s + 1) * G1_BK);
            cpB((s + 1) * G1_BK, (s + 1) & 1);
        }
        compute(s & 1);
        if (s + 1 < G1_STAGES) {
            stsA((s + 1) & 1);
            CP_WAIT0();
            __syncthreads();
        }
    }

    const float bval = bias[0];
    const int g  = lane >> 2;
    const int tq = lane & 3;
    #pragma unroll
    for (int mi = 0; mi < 2; mi++)
        #pragma unroll
        for (int nt = 0; nt < 8; nt++) {
            int row = m0 + mi * 16 + g;
            int col = n0 + nt * 8 + tq * 2;
            int gr0 = rowBase + row;
            int gr1 = gr0 + 8;
            float* cc = acc[mi][nt];
            if (gr0 < N_NODES) {
                uint32_t o = pack2h(fmaxf(cc[0] + bval, 0.f),
                                    fmaxf(cc[1] + bval, 0.f));
                *(uint32_t*)(C + (size_t)gr0 * NHID + col) = o;
            }
            if (gr1 < N_NODES) {
                uint32_t o = pack2h(fmaxf(cc[2] + bval, 0.f),
                                    fmaxf(cc[3] + bval, 0.f));
                *(uint32_t*)(C + (size_t)gr1 * NHID + col) = o;
            }
        }
}

// ===========================================================================
// GEMM2 (mma.sync fp16 x fp16): h2 = h @ W2 + b2
// A (fp16 h) loaded directly via cp.async. CTA 128 rows, 8 warps x 16 rows.
// ===========================================================================
#define G2_A_ST   16384                 // 128 rows x 128B
#define G2_W2_OFF 32768
#define G2_W2_CH  6144                  // 48 rows x 128B (40 used, pad for ldsm)
#define G2_SMEM   (32768 + 4 * G2_W2_CH)   // 57344

__global__ void __launch_bounds__(256, 1) gemm2_mma_kernel(
    const __half* __restrict__ A,     // g_hh [N, 256]
    const float* __restrict__ bias,
    float* __restrict__ C)            // g_h2 [N, 40]
{
    extern __shared__ char smem[];
    const uint32_t sbase = smem_u32(smem);
    const int tid  = threadIdx.x;
    const int wid  = tid >> 5;
    const int lane = tid & 31;
    const int rowBase = blockIdx.x * 128;
    const int m0 = wid * 16;

    // async-load W2 chunk tiles (4 chunks x 40 rows x 8 segs x 16B)
    for (int idx = tid; idx < 4 * 40 * 8; idx += 256) {
        int ch  = idx / 320;
        int rem = idx - ch * 320;
        int n   = rem >> 3;
        int seg = rem & 7;
        const __half* src = g_w2t + (size_t)n * NHID + ch * 64 + seg * 8;
        uint32_t off = n * 128 + seg * 16;
        cpasync16(sbase + G2_W2_OFF + ch * G2_W2_CH + sw128(off), src);
    }
    CP_COMMIT();

    float acc[5][4];
    #pragma unroll
    for (int j = 0; j < 5; j++)
        #pragma unroll
        for (int q = 0; q < 4; q++) acc[j][q] = 0.f;

    auto cpA = [&](int k0, int stage) {
        uint32_t ab = sbase + stage * G2_A_ST;
        #pragma unroll
        for (int it = 0; it < 4; it++) {
            int s = tid + it * 256;          // 0..1023
            int r   = s >> 3;                // 0..127
            int seg = s & 7;
            int gr = rowBase + r;
            if (gr >= N_NODES) gr = N_NODES - 1;   // clamp (rows unwritten anyway)
            const __half* src = A + (size_t)gr * NHID + k0 + seg * 8;
            uint32_t off = r * 128 + seg * 16;
            cpasync16(ab + sw128(off), src);
        }
        CP_COMMIT();
    };

    auto compute = [&](int stage, int ch) {
        uint32_t ab = sbase + stage * G2_A_ST;
        uint32_t bb = sbase + G2_W2_OFF + ch * G2_W2_CH;
        const int q  = lane >> 3;
        const int rr = lane & 7;
        #pragma unroll
        for (int k16 = 0; k16 < 4; k16++) {
            int cb = k16 * 2;
            uint32_t ah[4];
            {
                int row = m0 + (q & 1) * 8 + rr;
                uint32_t offh = row * 128 + (cb + (q >> 1)) * 16;
                ldsm4(ab + sw128(offh), ah);
            }
            uint32_t bh[3][4];
            #pragma unroll
            for (int nj = 0; nj < 3; nj++) {
                int row = nj * 16 + (q & 1) * 8 + rr;
                uint32_t offh = row * 128 + (cb + (q >> 1)) * 16;
                ldsm4(bb + sw128(offh), bh[nj]);
            }
            #pragma unroll
            for (int nt = 0; nt < 5; nt++) {
                int nj = nt >> 1, hh = nt & 1;
                mma16816(acc[nt], ah, bh[nj][hh], bh[nj][2 + hh]);
            }
        }
    };

    cpA(0, 0);
    CP_WAIT0();        // waits W2 tiles + first A stage
    __syncthreads();

    for (int ch = 0; ch < 4; ch++) {
        if (ch + 1 < 4) cpA((ch + 1) * 64, (ch + 1) & 1);
        compute(ch & 1, ch);
        if (ch + 1 < 4) {
            CP_WAIT0();
            __syncthreads();
        }
    }

    const float bval = bias[0];
    const int g  = lane >> 2;
    const int tq = lane & 3;
    #pragma unroll
    for (int nt = 0; nt < 5; nt++) {
        int col = nt * 8 + tq * 2;
        int gr0 = rowBase + m0 + g;
        int gr1 = gr0 + 8;
        if (gr0 < N_NODES) {
            float2 o; o.x = acc[nt][0] + bval; o.y = acc[nt][1] + bval;
            *(float2*)(C + (size_t)gr0 * NCLASS + col) = o;
        }
        if (gr1 < N_NODES) {
            float2 o; o.x = acc[nt][2] + bval; o.y = acc[nt][3] + bval;
            *(float2*)(C + (size_t)gr1 * NCLASS + col) = o;
        }
    }
}

// ---------------------------------------------------------------------------
// CSR build: histogram -> 2-level exclusive scan -> scatter
// ---------------------------------------------------------------------------
__global__ void zero_counts_kernel()
{
    int i = blockIdx.x * blockDim.x + threadIdx.x;
    if (i < N_NODES) g_cnt[i] = 0;
}

__global__ void histogram_kernel(const int* __restrict__ row)
{
    int e = blockIdx.x * blockDim.x + threadIdx.x;
    if (e < E_EDGES) atomicAdd(&g_cnt[row[e]], 1);
}

__global__ void __launch_bounds__(SCAN_BLK) scan1_kernel()
{
    __shared__ int s[SCAN_BLK];
    int gid = blockIdx.x * SCAN_BLK + threadIdx.x;
    int x = (gid < N_NODES) ? g_cnt[gid] : 0;
    s[threadIdx.x] = x;
    __syncthreads();
    #pragma unroll
    for (int d = 1; d < SCAN_BLK; d <<= 1) {
        int t = (threadIdx.x >= d) ? s[threadIdx.x - d] : 0;
        __syncthreads();
        s[threadIdx.x] += t;
        __syncthreads();
    }
    if (gid < N_NODES) g_offl[gid] = s[threadIdx.x] - x;
    if (threadIdx.x == SCAN_BLK - 1) g_blk[blockIdx.x] = s[SCAN_BLK - 1];
}

__global__ void scan2_kernel()
{
    __shared__ int s[128];
    int tid = threadIdx.x;
    int x = (tid < NUM_SCAN_BLKS) ? g_blk[tid] : 0;
    s[tid] = x;
    __syncthreads();
    #pragma unroll
    for (int d = 1; d < 128; d <<= 1) {
        int t = (tid >= d) ? s[tid - d] : 0;
        __syncthreads();
        s[tid] += t;
        __syncthreads();
    }
    if (tid < NUM_SCAN_BLKS) g_blkoff[tid] = s[tid] - x;
}

__global__ void scan3_kernel()
{
    int i = blockIdx.x * blockDim.x + threadIdx.x;
    if (i < N_NODES) {
        int st = g_offl[i] + g_blkoff[i / SCAN_BLK];
        g_start[i]  = st;
        g_cursor[i] = st;
    }
    if (i == 0) g_start[N_NODES] = E_EDGES;
}

__global__ void scatter_kernel(const int* __restrict__ row,
                               const int* __restrict__ col,
                               const float* __restrict__ vals)
{
    int e = blockIdx.x * blockDim.x + threadIdx.x;
    if (e >= E_EDGES) return;
    int r = row[e];
    int pos = atomicAdd(&g_cursor[r], 1);
    int2 ev;
    ev.x = col[e];
    ev.y = __float_as_int((1.0f - ALPHA) * vals[e]);
    g_edges[pos] = ev;
}

// ---------------------------------------------------------------------------
// Pull-mode SpMM: 10 threads per row, one float4 segment per thread.
// ---------------------------------------------------------------------------
#define SPMM_TPB 320

__global__ void __launch_bounds__(SPMM_TPB) spmm_csr_kernel(
    const float* __restrict__ z,
    const float* __restrict__ h2,
    float* __restrict__ znew)
{
    int t = blockIdx.x * SPMM_TPB + threadIdx.x;
    int r   = t / 10;
    int seg = t - r * 10;
    if (r >= N_NODES) return;

    int e0 = g_start[r];
    int e1 = g_start[r + 1];

    float4 acc = make_float4(0.f, 0.f, 0.f, 0.f);

    int e = e0;
    for (; e + 2 <= e1; e += 2) {
        int2 ev0 = __ldg(&g_edges[e]);
        int2 ev1 = __ldg(&g_edges[e + 1]);
        float v0 = __int_as_float(ev0.y);
        float v1 = __int_as_float(ev1.y);
        float4 a0 = __ldg((const float4*)(z + (size_t)ev0.x * NCLASS) + seg);
        float4 a1 = __ldg((const float4*)(z + (size_t)ev1.x * NCLASS) + seg);
        acc.x += v0 * a0.x + v1 * a1.x;
        acc.y += v0 * a0.y + v1 * a1.y;
        acc.z += v0 * a0.z + v1 * a1.z;
        acc.w += v0 * a0.w + v1 * a1.w;
    }
    if (e < e1) {
        int2 ev = __ldg(&g_edges[e]);
        float v = __int_as_float(ev.y);
        float4 a = __ldg((const float4*)(z + (size_t)ev.x * NCLASS) + seg);
        acc.x += v * a.x;
        acc.y += v * a.y;
        acc.z += v * a.z;
        acc.w += v * a.w;
    }

    float4 hv = __ldg((const float4*)(h2 + (size_t)r * NCLASS) + seg);
    float4 o;
    o.x = acc.x + ALPHA * hv.x;
    o.y = acc.y + ALPHA * hv.y;
    o.z = acc.z + ALPHA * hv.z;
    o.w = acc.w + ALPHA * hv.w;
    ((float4*)(znew + (size_t)r * NCLASS))[seg] = o;
}

// ---------------------------------------------------------------------------
// Row-wise log_softmax over 40 classes: one warp per row
// ---------------------------------------------------------------------------
__global__ void logsoftmax_kernel(const float* __restrict__ z,
                                  float* __restrict__ out)
{
    int gtid = blockIdx.x * blockDim.x + threadIdx.x;
    int warp = gtid / 32;
    int lane = gtid % 32;
    if (warp >= N_NODES) return;

    const float* zr = z + (size_t)warp * NCLASS;
    float v0 = zr[lane];
    float v1 = (lane < NCLASS - 32) ? zr[lane + 32] : -INFINITY;

    float m = fmaxf(v0, v1);
    #pragma unroll
    for (int o = 16; o > 0; o >>= 1)
        m = fmaxf(m, __shfl_xor_sync(0xFFFFFFFFu, m, o));

    float s = expf(v0 - m) + ((lane < NCLASS - 32) ? expf(v1 - m) : 0.f);
    #pragma unroll
    for (int o = 16; o > 0; o >>= 1)
        s += __shfl_xor_sync(0xFFFFFFFFu, s, o);

    float L = m + logf(s);
    out[(size_t)warp * NCLASS + lane] = v0 - L;
    if (lane < NCLASS - 32)
        out[(size_t)warp * NCLASS + lane + 32] = v1 - L;
}

// ---------------------------------------------------------------------------
extern "C" void kernel_launch(void* const* d_in, const int* in_sizes, int n_in,
                              void* d_out, int out_size)
{
    const float* x    = (const float*)d_in[0];
    const int*   row  = (const int*)  d_in[1];
    const int*   col  = (const int*)  d_in[2];
    const float* vals = (const float*)d_in[3];
    const float* W1   = (const float*)d_in[4];
    const float* b1   = (const float*)d_in[5];
    const float* W2   = (const float*)d_in[6];
    const float* b2   = (const float*)d_in[7];
    float* out = (float*)d_out;

    __half* hh;
    float *h2, *za, *zb;
    cudaGetSymbolAddress((void**)&hh, g_hh);
    cudaGetSymbolAddress((void**)&h2, g_h2);
    cudaGetSymbolAddress((void**)&za, g_za);
    cudaGetSymbolAddress((void**)&zb, g_zb);

    cudaFuncSetAttribute(gemm1_mma_kernel,
                         cudaFuncAttributeMaxDynamicSharedMemorySize, G1_SMEM);
    cudaFuncSetAttribute(gemm2_mma_kernel,
                         cudaFuncAttributeMaxDynamicSharedMemorySize, G2_SMEM);

    // Launch order: gemm1 is our 4th launch (ncu profiles our #4).
    prep_w1t_kernel<<<(NHID * NFEAT + 255) / 256, 256>>>(W1);              // 1
    prep_w2t_kernel<<<(NCLASS * NHID + 255) / 256, 256>>>(W2);             // 2
    zero_counts_kernel<<<(N_NODES + 255) / 256, 256>>>();                  // 3
    gemm1_mma_kernel<<<(N_NODES + G1_BM - 1) / G1_BM, 256, G1_SMEM>>>(x, b1, hh); // 4
    histogram_kernel<<<(E_EDGES + 255) / 256, 256>>>(row);                 // 5
    scan1_kernel<<<NUM_SCAN_BLKS, SCAN_BLK>>>();                           // 6
    scan2_kernel<<<1, 128>>>();                                            // 7
    scan3_kernel<<<(N_NODES + 255) / 256, 256>>>();                        // 8
    scatter_kernel<<<(E_EDGES + 255) / 256, 256>>>(row, col, vals);        // 9
    gemm2_mma_kernel<<<(N_NODES + 127) / 128, 256, G2_SMEM>>>(hh, b2, h2); // 10

    // APPNP propagation
    const int spmm_grid = (N_NODES * 10 + SPMM_TPB - 1) / SPMM_TPB;
    const float* zin = h2;
    float* bufs[2] = { za, zb };
    for (int it = 0; it < NLAYERS; it++) {
        float* zout = bufs[it & 1];
        spmm_csr_kernel<<<spmm_grid, SPMM_TPB>>>(zin, h2, zout);
        zin = zout;
    }

    logsoftmax_kernel<<<(N_NODES * 32 + 255) / 256, 256>>>(zin, out);
}

// round 14
// speedup vs baseline: 1.1116x; 1.0331x over previous
#include <cuda_runtime.h>
#include <cuda_fp16.h>
#include <math.h>
#include <stdint.h>

#define N_NODES 100000
#define E_EDGES 1600000
#define NFEAT   512
#define NHID    256
#define NCLASS  40
#define NLAYERS 10
#define ALPHA   0.1f

#define SCAN_BLK 1024
#define NUM_SCAN_BLKS ((N_NODES + SCAN_BLK - 1) / SCAN_BLK)   // 98

// Scratch (static device globals — allocation-free rule)
__device__ __half g_hh[N_NODES * NHID];   // fp16 relu(x@W1+b1)
__device__ float g_h2[N_NODES * NCLASS];  // h@W2+b2  (z_0)
__device__ float g_za[N_NODES * NCLASS];
__device__ float g_zb[N_NODES * NCLASS];

// W1 transposed, fp16: [NHID][NFEAT]
__device__ __half g_w1t[NHID * NFEAT];
// W2 transposed, fp16: [NCLASS][NHID]
__device__ __half g_w2t[NCLASS * NHID];

// CSR build scratch
__device__ int  g_cnt   [N_NODES];
__device__ int  g_offl  [N_NODES];
__device__ int  g_start [N_NODES + 1];
__device__ int  g_cursor[N_NODES];
__device__ int  g_blk   [NUM_SCAN_BLKS];
__device__ int  g_blkoff[NUM_SCAN_BLKS];
__device__ int2 g_edges [E_EDGES];

// ===========================================================================
// helpers (baseline PTX only: ldmatrix / mma.sync / cp.async)
// ===========================================================================
__device__ __forceinline__ uint32_t smem_u32(const void* p) {
    uint32_t a;
    asm("{ .reg .u64 t; cvta.to.shared.u64 t, %1; cvt.u32.u64 %0, t; }"
        : "=r"(a) : "l"(p));
    return a;
}

__device__ __forceinline__ void ldsm4(uint32_t addr, uint32_t* r) {
    asm volatile("ldmatrix.sync.aligned.m8n8.x4.shared.b16 {%0,%1,%2,%3}, [%4];"
        : "=r"(r[0]), "=r"(r[1]), "=r"(r[2]), "=r"(r[3]) : "r"(addr));
}

// fp16 MMA, fp32 accumulate
__device__ __forceinline__ void mma16816(float* c, const uint32_t* a,
                                         uint32_t b0, uint32_t b1) {
    asm volatile(
        "mma.sync.aligned.m16n8k16.row.col.f32.f16.f16.f32 "
        "{%0,%1,%2,%3}, {%4,%5,%6,%7}, {%8,%9}, {%0,%1,%2,%3};"
        : "+f"(c[0]), "+f"(c[1]), "+f"(c[2]), "+f"(c[3])
        : "r"(a[0]), "r"(a[1]), "r"(a[2]), "r"(a[3]), "r"(b0), "r"(b1));
}

__device__ __forceinline__ void cpasync16(uint32_t saddr, const void* gptr) {
    asm volatile("cp.async.cg.shared.global [%0], [%1], 16;"
                 :: "r"(saddr), "l"(gptr) : "memory");
}
#define CP_COMMIT() asm volatile("cp.async.commit_group;" ::: "memory")
#define CP_WAIT0()  asm volatile("cp.async.wait_group 0;" ::: "memory")

__device__ __forceinline__ uint32_t sw128(uint32_t off) {
    return off ^ ((off >> 3) & 0x70);
}

__device__ __forceinline__ uint32_t pack2h(float a, float b) {
    __half2 h = __floats2half2_rn(a, b);
    return *(uint32_t*)&h;
}

// ===========================================================================
// Prep: W1T / W2T fp16
// ===========================================================================
__global__ void prep_w1t_kernel(const float* __restrict__ W1)
{
    int i = blockIdx.x * blockDim.x + threadIdx.x;
    if (i >= NHID * NFEAT) return;
    int n = i / NFEAT, k = i % NFEAT;
    g_w1t[i] = __float2half(W1[(size_t)k * NHID + n]);
}

__global__ void prep_w2t_kernel(const float* __restrict__ W2)
{
    int i = blockIdx.x * blockDim.x + threadIdx.x;
    if (i >= NCLASS * NHID) return;
    int n = i / NHID, k = i % NHID;
    g_w2t[i] = __float2half(W2[(size_t)k * NCLASS + n]);
}

// ===========================================================================
// GEMM1 (mma.sync fp16 x fp16): h = relu(x @ W1 + b1), output fp16
// CTA 64x256, 256 threads / 8 warps (2m x 4n), warp tile 32x64.
// K staged at 64, double buffered smem, 2 CTAs/SM.
// B fragments double-buffered in registers.
// ===========================================================================
#define G1_BM 64
#define G1_BN 256
#define G1_BK 64
#define G1_STAGES (NFEAT / G1_BK)      // 8
#define G1_A_OFF 0
#define G1_B_OFF 8192
#define G1_STAGE_BYTES 40960           // 8KB A + 32KB B
#define G1_SMEM (2 * G1_STAGE_BYTES)   // 81920

__global__ void __launch_bounds__(256, 2) gemm1_mma_kernel(
    const float* __restrict__ A,
    const float* __restrict__ bias,
    __half* __restrict__ C)
{
    extern __shared__ char smem[];
    const uint32_t sbase = smem_u32(smem);
    const int tid  = threadIdx.x;
    const int lane = tid & 31;
    const int wid  = tid >> 5;
    const int rowBase = blockIdx.x * G1_BM;

    const int warp_m = wid & 1;        // 0..1
    const int warp_n = wid >> 1;       // 0..3
    const int m0 = warp_m * 32;
    const int n0 = warp_n * 64;

    float acc[2][8][4];
    #pragma unroll
    for (int i = 0; i < 2; i++)
        #pragma unroll
        for (int j = 0; j < 8; j++)
            #pragma unroll
            for (int q = 0; q < 4; q++) acc[i][j][q] = 0.f;

    const int agr = tid >> 2;          // row 0..63
    const int aoq = tid & 3;           // 16-float group within k64

    float a_st[16];

    auto ldgA = [&](int k0) {
        int gr = rowBase + agr;
        if (gr < N_NODES) {
            const float* p = A + (size_t)gr * NFEAT + k0 + aoq * 16;
            #pragma unroll
            for (int v = 0; v < 4; v++) {
                float4 t = *(const float4*)(p + v * 4);
                a_st[v*4+0]=t.x; a_st[v*4+1]=t.y; a_st[v*4+2]=t.z; a_st[v*4+3]=t.w;
            }
        } else {
            #pragma unroll
            for (int q = 0; q < 16; q++) a_st[q] = 0.f;
        }
    };
    auto cpB = [&](int k0, int stage) {
        uint32_t bb = sbase + stage * G1_STAGE_BYTES + G1_B_OFF;
        #pragma unroll
        for (int it = 0; it < 8; it++) {
            int s = tid + it * 256;            // 0..2047
            int n   = s >> 3;                  // 0..255
            int seg = s & 7;
            size_t gi = (size_t)n * NFEAT + k0 + seg * 8;
            uint32_t off = n * 128 + seg * 16;
            cpasync16(bb + sw128(off), g_w1t + gi);
        }
        CP_COMMIT();
    };
    auto stsA = [&](int stage) {
        uint4 q0, q1;
        q0.x = pack2h(a_st[0],  a_st[1]);
        q0.y = pack2h(a_st[2],  a_st[3]);
        q0.z = pack2h(a_st[4],  a_st[5]);
        q0.w = pack2h(a_st[6],  a_st[7]);
        q1.x = pack2h(a_st[8],  a_st[9]);
        q1.y = pack2h(a_st[10], a_st[11]);
        q1.z = pack2h(a_st[12], a_st[13]);
        q1.w = pack2h(a_st[14], a_st[15]);
        uint32_t offh = agr * 128 + aoq * 32;
        char* ab = smem + stage * G1_STAGE_BYTES + G1_A_OFF;
        *(uint4*)(ab + sw128(offh))      = q0;
        *(uint4*)(ab + sw128(offh + 16)) = q1;
    };

    auto compute = [&](int stage) {
        uint32_t ab = sbase + stage * G1_STAGE_BYTES + G1_A_OFF;
        uint32_t bb = sbase + stage * G1_STAGE_BYTES + G1_B_OFF;
        const int q  = lane >> 3;
        const int rr = lane & 7;

        uint32_t bf[2][4][4];   // double-buffered B fragments
        #pragma unroll
        for (int nj = 0; nj < 4; nj++) {
            int row = n0 + nj * 16 + (q & 1) * 8 + rr;
            uint32_t offh = row * 128 + (q >> 1) * 16;
            ldsm4(bb + sw128(offh), bf[0][nj]);
        }
        #pragma unroll
        for (int k16 = 0; k16 < 4; k16++) {
            int cur = k16 & 1;
            if (k16 < 3) {
                int cbn = (k16 + 1) * 2;
                #pragma unroll
                for (int nj = 0; nj < 4; nj++) {
                    int row = n0 + nj * 16 + (q & 1) * 8 + rr;
                    uint32_t offh = row * 128 + (cbn + (q >> 1)) * 16;
                    ldsm4(bb + sw128(offh), bf[cur ^ 1][nj]);
                }
            }
            int cb = k16 * 2;
            uint32_t ah[2][4];
            #pragma unroll
            for (int mi = 0; mi < 2; mi++) {
                int row = m0 + mi * 16 + (q & 1) * 8 + rr;
                uint32_t offh = row * 128 + (cb + (q >> 1)) * 16;
                ldsm4(ab + sw128(offh), ah[mi]);
            }
            #pragma unroll
            for (int nj = 0; nj < 4; nj++)
                #pragma unroll
                for (int mi = 0; mi < 2; mi++)
                    #pragma unroll
                    for (int hh = 0; hh < 2; hh++) {
                        float* cc = acc[mi][nj * 2 + hh];
                        mma16816(cc, ah[mi], bf[cur][nj][hh], bf[cur][nj][2 + hh]);
                    }
        }
    };

    ldgA(0); cpB(0, 0); stsA(0);
    CP_WAIT0();
    __syncthreads();

    for (int s = 0; s < G1_STAGES; s++) {
        if (s + 1 < G1_STAGES) {
            ldgA((s + 1) * G1_BK);
            cpB((s + 1) * G1_BK, (s + 1) & 1);
        }
        compute(s & 1);
        if (s + 1 < G1_STAGES) {
            stsA((s + 1) & 1);
            CP_WAIT0();
            __syncthreads();
        }
    }

    const float bval = bias[0];
    const int g  = lane >> 2;
    const int tq = lane & 3;
    #pragma unroll
    for (int mi = 0; mi < 2; mi++)
        #pragma unroll
        for (int nt = 0; nt < 8; nt++) {
            int row = m0 + mi * 16 + g;
            int col = n0 + nt * 8 + tq * 2;
            int gr0 = rowBase + row;
            int gr1 = gr0 + 8;
            float* cc = acc[mi][nt];
            if (gr0 < N_NODES) {
                uint32_t o = pack2h(fmaxf(cc[0] + bval, 0.f),
                                    fmaxf(cc[1] + bval, 0.f));
                *(uint32_t*)(C + (size_t)gr0 * NHID + col) = o;
            }
            if (gr1 < N_NODES) {
                uint32_t o = pack2h(fmaxf(cc[2] + bval, 0.f),
                                    fmaxf(cc[3] + bval, 0.f));
                *(uint32_t*)(C + (size_t)gr1 * NHID + col) = o;
            }
        }
}

// ===========================================================================
// GEMM2 (mma.sync fp16 x fp16): h2 = h @ W2 + b2
// ===========================================================================
#define G2_A_ST   16384                 // 128 rows x 128B
#define G2_W2_OFF 32768
#define G2_W2_CH  6144                  // 48 rows x 128B (40 used, pad for ldsm)
#define G2_SMEM   (32768 + 4 * G2_W2_CH)   // 57344

__global__ void __launch_bounds__(256, 1) gemm2_mma_kernel(
    const __half* __restrict__ A,     // g_hh [N, 256]
    const float* __restrict__ bias,
    float* __restrict__ C)            // g_h2 [N, 40]
{
    extern __shared__ char smem[];
    const uint32_t sbase = smem_u32(smem);
    const int tid  = threadIdx.x;
    const int wid  = tid >> 5;
    const int lane = tid & 31;
    const int rowBase = blockIdx.x * 128;
    const int m0 = wid * 16;

    for (int idx = tid; idx < 4 * 40 * 8; idx += 256) {
        int ch  = idx / 320;
        int rem = idx - ch * 320;
        int n   = rem >> 3;
        int seg = rem & 7;
        const __half* src = g_w2t + (size_t)n * NHID + ch * 64 + seg * 8;
        uint32_t off = n * 128 + seg * 16;
        cpasync16(sbase + G2_W2_OFF + ch * G2_W2_CH + sw128(off), src);
    }
    CP_COMMIT();

    float acc[5][4];
    #pragma unroll
    for (int j = 0; j < 5; j++)
        #pragma unroll
        for (int q = 0; q < 4; q++) acc[j][q] = 0.f;

    auto cpA = [&](int k0, int stage) {
        uint32_t ab = sbase + stage * G2_A_ST;
        #pragma unroll
        for (int it = 0; it < 4; it++) {
            int s = tid + it * 256;          // 0..1023
            int r   = s >> 3;                // 0..127
            int seg = s & 7;
            int gr = rowBase + r;
            if (gr >= N_NODES) gr = N_NODES - 1;
            const __half* src = A + (size_t)gr * NHID + k0 + seg * 8;
            uint32_t off = r * 128 + seg * 16;
            cpasync16(ab + sw128(off), src);
        }
        CP_COMMIT();
    };

    auto compute = [&](int stage, int ch) {
        uint32_t ab = sbase + stage * G2_A_ST;
        uint32_t bb = sbase + G2_W2_OFF + ch * G2_W2_CH;
        const int q  = lane >> 3;
        const int rr = lane & 7;
        #pragma unroll
        for (int k16 = 0; k16 < 4; k16++) {
            int cb = k16 * 2;
            uint32_t ah[4];
            {
                int row = m0 + (q & 1) * 8 + rr;
                uint32_t offh = row * 128 + (cb + (q >> 1)) * 16;
                ldsm4(ab + sw128(offh), ah);
            }
            uint32_t bh[3][4];
            #pragma unroll
            for (int nj = 0; nj < 3; nj++) {
                int row = nj * 16 + (q & 1) * 8 + rr;
                uint32_t offh = row * 128 + (cb + (q >> 1)) * 16;
                ldsm4(bb + sw128(offh), bh[nj]);
            }
            #pragma unroll
            for (int nt = 0; nt < 5; nt++) {
                int nj = nt >> 1, hh = nt & 1;
                mma16816(acc[nt], ah, bh[nj][hh], bh[nj][2 + hh]);
            }
        }
    };

    cpA(0, 0);
    CP_WAIT0();
    __syncthreads();

    for (int ch = 0; ch < 4; ch++) {
        if (ch + 1 < 4) cpA((ch + 1) * 64, (ch + 1) & 1);
        compute(ch & 1, ch);
        if (ch + 1 < 4) {
            CP_WAIT0();
            __syncthreads();
        }
    }

    const float bval = bias[0];
    const int g  = lane >> 2;
    const int tq = lane & 3;
    #pragma unroll
    for (int nt = 0; nt < 5; nt++) {
        int col = nt * 8 + tq * 2;
        int gr0 = rowBase + m0 + g;
        int gr1 = gr0 + 8;
        if (gr0 < N_NODES) {
            float2 o; o.x = acc[nt][0] + bval; o.y = acc[nt][1] + bval;
            *(float2*)(C + (size_t)gr0 * NCLASS + col) = o;
        }
        if (gr1 < N_NODES) {
            float2 o; o.x = acc[nt][2] + bval; o.y = acc[nt][3] + bval;
            *(float2*)(C + (size_t)gr1 * NCLASS + col) = o;
        }
    }
}

// ---------------------------------------------------------------------------
// CSR build: histogram -> 2-level exclusive scan -> scatter
// ---------------------------------------------------------------------------
__global__ void zero_counts_kernel()
{
    int i = blockIdx.x * blockDim.x + threadIdx.x;
    if (i < N_NODES) g_cnt[i] = 0;
}

__global__ void histogram_kernel(const int* __restrict__ row)
{
    int e = blockIdx.x * blockDim.x + threadIdx.x;
    if (e < E_EDGES) atomicAdd(&g_cnt[row[e]], 1);
}

__global__ void __launch_bounds__(SCAN_BLK) scan1_kernel()
{
    __shared__ int s[SCAN_BLK];
    int gid = blockIdx.x * SCAN_BLK + threadIdx.x;
    int x = (gid < N_NODES) ? g_cnt[gid] : 0;
    s[threadIdx.x] = x;
    __syncthreads();
    #pragma unroll
    for (int d = 1; d < SCAN_BLK; d <<= 1) {
        int t = (threadIdx.x >= d) ? s[threadIdx.x - d] : 0;
        __syncthreads();
        s[threadIdx.x] += t;
        __syncthreads();
    }
    if (gid < N_NODES) g_offl[gid] = s[threadIdx.x] - x;
    if (threadIdx.x == SCAN_BLK - 1) g_blk[blockIdx.x] = s[SCAN_BLK - 1];
}

__global__ void scan2_kernel()
{
    __shared__ int s[128];
    int tid = threadIdx.x;
    int x = (tid < NUM_SCAN_BLKS) ? g_blk[tid] : 0;
    s[tid] = x;
    __syncthreads();
    #pragma unroll
    for (int d = 1; d < 128; d <<= 1) {
        int t = (tid >= d) ? s[tid - d] : 0;
        __syncthreads();
        s[tid] += t;
        __syncthreads();
    }
    if (tid < NUM_SCAN_BLKS) g_blkoff[tid] = s[tid] - x;
}

__global__ void scan3_kernel()
{
    int i = blockIdx.x * blockDim.x + threadIdx.x;
    if (i < N_NODES) {
        int st = g_offl[i] + g_blkoff[i / SCAN_BLK];
        g_start[i]  = st;
        g_cursor[i] = st;
    }
    if (i == 0) g_start[N_NODES] = E_EDGES;
}

__global__ void scatter_kernel(const int* __restrict__ row,
                               const int* __restrict__ col,
                               const float* __restrict__ vals)
{
    int e = blockIdx.x * blockDim.x + threadIdx.x;
    if (e >= E_EDGES) return;
    int r = row[e];
    int pos = atomicAdd(&g_cursor[r], 1);
    int2 ev;
    ev.x = col[e];
    ev.y = __float_as_int((1.0f - ALPHA) * vals[e]);
    g_edges[pos] = ev;
}

// ---------------------------------------------------------------------------
// Pull-mode SpMM: 10 threads per row, one float4 segment per thread.
// ---------------------------------------------------------------------------
#define SPMM_TPB 320

__global__ void __launch_bounds__(SPMM_TPB) spmm_csr_kernel(
    const float* __restrict__ z,
    const float* __restrict__ h2,
    float* __restrict__ znew)
{
    int t = blockIdx.x * SPMM_TPB + threadIdx.x;
    int r   = t / 10;
    int seg = t - r * 10;
    if (r >= N_NODES) return;

    int e0 = g_start[r];
    int e1 = g_start[r + 1];

    float4 acc = make_float4(0.f, 0.f, 0.f, 0.f);

    int e = e0;
    for (; e + 2 <= e1; e += 2) {
        int2 ev0 = __ldg(&g_edges[e]);
        int2 ev1 = __ldg(&g_edges[e + 1]);
        float v0 = __int_as_float(ev0.y);
        float v1 = __int_as_float(ev1.y);
        float4 a0 = __ldg((const float4*)(z + (size_t)ev0.x * NCLASS) + seg);
        float4 a1 = __ldg((const float4*)(z + (size_t)ev1.x * NCLASS) + seg);
        acc.x += v0 * a0.x + v1 * a1.x;
        acc.y += v0 * a0.y + v1 * a1.y;
        acc.z += v0 * a0.z + v1 * a1.z;
        acc.w += v0 * a0.w + v1 * a1.w;
    }
    if (e < e1) {
        int2 ev = __ldg(&g_edges[e]);
        float v = __int_as_float(ev.y);
        float4 a = __ldg((const float4*)(z + (size_t)ev.x * NCLASS) + seg);
        acc.x += v * a.x;
        acc.y += v * a.y;
        acc.z += v * a.z;
        acc.w += v * a.w;
    }

    float4 hv = __ldg((const float4*)(h2 + (size_t)r * NCLASS) + seg);
    float4 o;
    o.x = acc.x + ALPHA * hv.x;
    o.y = acc.y + ALPHA * hv.y;
    o.z = acc.z + ALPHA * hv.z;
    o.w = acc.w + ALPHA * hv.w;
    ((float4*)(znew + (size_t)r * NCLASS))[seg] = o;
}

// ---------------------------------------------------------------------------
// Row-wise log_softmax over 40 classes: one warp per row
// ---------------------------------------------------------------------------
__global__ void logsoftmax_kernel(const float* __restrict__ z,
                                  float* __restrict__ out)
{
    int gtid = blockIdx.x * blockDim.x + threadIdx.x;
    int warp = gtid / 32;
    int lane = gtid % 32;
    if (warp >= N_NODES) return;

    const float* zr = z + (size_t)warp * NCLASS;
    float v0 = zr[lane];
    float v1 = (lane < NCLASS - 32) ? zr[lane + 32] : -INFINITY;

    float m = fmaxf(v0, v1);
    #pragma unroll
    for (int o = 16; o > 0; o >>= 1)
        m = fmaxf(m, __shfl_xor_sync(0xFFFFFFFFu, m, o));

    float s = expf(v0 - m) + ((lane < NCLASS - 32) ? expf(v1 - m) : 0.f);
    #pragma unroll
    for (int o = 16; o > 0; o >>= 1)
        s += __shfl_xor_sync(0xFFFFFFFFu, s, o);

    float L = m + logf(s);
    out[(size_t)warp * NCLASS + lane] = v0 - L;
    if (lane < NCLASS - 32)
        out[(size_t)warp * NCLASS + lane + 32] = v1 - L;
}

// ---------------------------------------------------------------------------
// Host-side one-time resources for graph fork/join (host objects only —
// no device memory). Created on first call; identical GPU work every call.
// ---------------------------------------------------------------------------
static cudaStream_t g_s2 = nullptr;
static cudaEvent_t  g_evFork = nullptr;
static cudaEvent_t  g_evJoin = nullptr;

extern "C" void kernel_launch(void* const* d_in, const int* in_sizes, int n_in,
                              void* d_out, int out_size)
{
    const float* x    = (const float*)d_in[0];
    const int*   row  = (const int*)  d_in[1];
    const int*   col  = (const int*)  d_in[2];
    const float* vals = (const float*)d_in[3];
    const float* W1   = (const float*)d_in[4];
    const float* b1   = (const float*)d_in[5];
    const float* W2   = (const float*)d_in[6];
    const float* b2   = (const float*)d_in[7];
    float* out = (float*)d_out;

    __half* hh;
    float *h2, *za, *zb;
    cudaGetSymbolAddress((void**)&hh, g_hh);
    cudaGetSymbolAddress((void**)&h2, g_h2);
    cudaGetSymbolAddress((void**)&za, g_za);
    cudaGetSymbolAddress((void**)&zb, g_zb);

    cudaFuncSetAttribute(gemm1_mma_kernel,
                         cudaFuncAttributeMaxDynamicSharedMemorySize, G1_SMEM);
    cudaFuncSetAttribute(gemm2_mma_kernel,
                         cudaFuncAttributeMaxDynamicSharedMemorySize, G2_SMEM);

    if (g_s2 == nullptr) {
        cudaStreamCreateWithFlags(&g_s2, cudaStreamNonBlocking);
        cudaEventCreateWithFlags(&g_evFork, cudaEventDisableTiming);
        cudaEventCreateWithFlags(&g_evJoin, cudaEventDisableTiming);
    }

    // Fork: CSR build runs on g_s2 in parallel with the MLP on the main stream.
    cudaEventRecord(g_evFork, 0);
    cudaStreamWaitEvent(g_s2, g_evFork, 0);

    // Main-stream MLP chain (kernel launches #1,#2,#4,#10 in API order;
    // gemm1 stays the 4th kernel launch for ncu).
    prep_w1t_kernel<<<(NHID * NFEAT + 255) / 256, 256>>>(W1);               // k1
    prep_w2t_kernel<<<(NCLASS * NHID + 255) / 256, 256>>>(W2);              // k2
    zero_counts_kernel<<<(N_NODES + 255) / 256, 256, 0, g_s2>>>();          // k3 (s2)
    gemm1_mma_kernel<<<(N_NODES + G1_BM - 1) / G1_BM, 256, G1_SMEM>>>(x, b1, hh); // k4
    histogram_kernel<<<(E_EDGES + 255) / 256, 256, 0, g_s2>>>(row);         // k5 (s2)
    scan1_kernel<<<NUM_SCAN_BLKS, SCAN_BLK, 0, g_s2>>>();                   // k6 (s2)
    scan2_kernel<<<1, 128, 0, g_s2>>>();                                    // k7 (s2)
    scan3_kernel<<<(N_NODES + 255) / 256, 256, 0, g_s2>>>();                // k8 (s2)
    scatter_kernel<<<(E_EDGES + 255) / 256, 256, 0, g_s2>>>(row, col, vals);// k9 (s2)
    gemm2_mma_kernel<<<(N_NODES + 127) / 128, 256, G2_SMEM>>>(hh, b2, h2);  // k10

    // Join: spmm needs both h2 (main) and CSR (s2).
    cudaEventRecord(g_evJoin, g_s2);
    cudaStreamWaitEvent(0, g_evJoin, 0);

    // APPNP propagation
    const int spmm_grid = (N_NODES * 10 + SPMM_TPB - 1) / SPMM_TPB;
    const float* zin = h2;
    float* bufs[2] = { za, zb };
    for (int it = 0; it < NLAYERS; it++) {
        float* zout = bufs[it & 1];
        spmm_csr_kernel<<<spmm_grid, SPMM_TPB>>>(zin, h2, zout);
        zin = zout;
    }

    logsoftmax_kernel<<<(N_NODES * 32 + 255) / 256, 256>>>(zin, out);
}